// round 3
// baseline (speedup 1.0000x reference)
#include <cuda_runtime.h>

#define BB      256
#define MAXLEN  10000
#define NWORDS  (MAXLEN * 9)        // 90000 words per batch
#define NV4     (NWORDS / 4)        // 22500 float4 per batch
#define NATOMS  2000
#define NBONDS  1999
#define NANG    1998
#define NTOR    1997
#define NBT     50
#define NAT     100
#define NTT     200
#define PTOT    (NBT + NAT + NTT)   // 350
#define EPSF    1e-8f
#define NTHR    512

// dynamic smem layout (word offsets)
#define OFF_COORD 0
#define N_COORD   (3 * NATOMS)      // 6000
#define OFF_BOND  (OFF_COORD + N_COORD)
#define N_BOND    (3 * NBONDS)      // 5997
#define OFF_ANG   (OFF_BOND + N_BOND)
#define N_ANG_W   (4 * NANG)        // 7992
#define OFF_TOR   (OFF_ANG + N_ANG_W)
#define N_TOR_W   (5 * NTOR)        // 9985
#define OFF_OPT   (OFF_TOR + N_TOR_W)
#define OFF_MAP   (OFF_OPT + PTOT * 3)
#define OFF_WARP  (OFF_MAP + PTOT)
#define SMEM_WORDS (OFF_WARP + 16)
#define SMEM_BYTES (SMEM_WORDS * 4)

__global__ __launch_bounds__(NTHR)
void energy_kernel(const float* __restrict__ feats,
                   const int*   __restrict__ lengths,
                   const float* __restrict__ opt,
                   const float* __restrict__ btype,
                   const float* __restrict__ atype,
                   const float* __restrict__ ttype,
                   float*       __restrict__ out)
{
    extern __shared__ float sm[];
    float* scoord = sm + OFF_COORD;
    float* sbond  = sm + OFF_BOND;
    float* sang   = sm + OFF_ANG;
    float* stor   = sm + OFF_TOR;
    float* sopt   = sm + OFF_OPT;
    int*   smap   = (int*)(sm + OFF_MAP);
    float* swarp  = sm + OFF_WARP;

    const int b   = blockIdx.x;
    const int tid = threadIdx.x;
    const float* f = feats + (size_t)b * NWORDS;
    const float4* f4 = (const float4*)f;

    // ---- coalesced sweep over the whole 10000x9 slab, demux by column ----
    for (int idx = tid; idx < NV4; idx += NTHR) {
        float4 v = f4[idx];
        int w = idx * 4;
        float vv[4] = {v.x, v.y, v.z, v.w};
        #pragma unroll
        for (int c = 0; c < 4; c++, w++) {
            int m   = w / 9;
            int col = w - m * 9;
            float val = vv[c];
            if (col == 5)      { if (m < N_COORD) scoord[m] = val; }
            else if (col == 6) { if (m < N_BOND)  sbond[m]  = val; }
            else if (col == 7) { if (m < N_ANG_W) sang[m]   = val; }
            else if (col == 8) { if (m < N_TOR_W) stor[m]   = val; }
        }
    }
    // params + type maps
    for (int i = tid; i < PTOT * 3; i += NTHR)
        sopt[i] = opt[i];
    for (int i = tid; i < PTOT; i += NTHR) {
        float v;
        if      (i < NBT)       v = btype[i];
        else if (i < NBT + NAT) v = atype[i - NBT];
        else                    v = ttype[i - NBT - NAT];
        smap[i] = (int)v;
    }
    __syncthreads();

    const int nb = lengths[b * 9 + 6] / 3;
    const int na = lengths[b * 9 + 7] / 4;
    const int nt = lengths[b * 9 + 8] / 5;

    float acc = 0.0f;

    // ---- bonds: E = k * (r - r0)^2 ----
    for (int t = tid; t < NBONDS; t += NTHR) {
        if (t >= nb) continue;
        int i  = (int)sbond[3 * t + 0];
        int j  = (int)sbond[3 * t + 1];
        int ty = (int)sbond[3 * t + 2];
        float dx = scoord[3 * i + 0] - scoord[3 * j + 0];
        float dy = scoord[3 * i + 1] - scoord[3 * j + 1];
        float dz = scoord[3 * i + 2] - scoord[3 * j + 2];
        float r  = sqrtf(dx * dx + dy * dy + dz * dz + EPSF);
        int row  = smap[ty];
        float d  = r - sopt[row * 3 + 1];
        acc += sopt[row * 3 + 0] * d * d;
    }

    // ---- angles: E = k * (theta - theta0)^2 ----
    for (int t = tid; t < NANG; t += NTHR) {
        if (t >= na) continue;
        int i  = (int)sang[4 * t + 0];
        int j  = (int)sang[4 * t + 1];
        int k  = (int)sang[4 * t + 2];
        int ty = (int)sang[4 * t + 3];
        float ux = scoord[3 * i + 0] - scoord[3 * j + 0];
        float uy = scoord[3 * i + 1] - scoord[3 * j + 1];
        float uz = scoord[3 * i + 2] - scoord[3 * j + 2];
        float vx = scoord[3 * k + 0] - scoord[3 * j + 0];
        float vy = scoord[3 * k + 1] - scoord[3 * j + 1];
        float vz = scoord[3 * k + 2] - scoord[3 * j + 2];
        float duv = ux * vx + uy * vy + uz * vz;
        float duu = ux * ux + uy * uy + uz * uz;
        float dvv = vx * vx + vy * vy + vz * vz;
        float c   = duv * rsqrtf((duu + EPSF) * (dvv + EPSF));
        c = fminf(fmaxf(c, -1.0f + 1e-6f), 1.0f - 1e-6f);
        float theta = acosf(c);
        int row = smap[NBT + ty];
        float d = theta - sopt[row * 3 + 1];
        acc += sopt[row * 3 + 0] * d * d;
    }

    // ---- torsions: E = k * (1 + cos(n*phi - phi0)) ----
    for (int t = tid; t < NTOR; t += NTHR) {
        if (t >= nt) continue;
        int i  = (int)stor[5 * t + 0];
        int j  = (int)stor[5 * t + 1];
        int k  = (int)stor[5 * t + 2];
        int l  = (int)stor[5 * t + 3];
        int ty = (int)stor[5 * t + 4];

        float b1x = scoord[3 * j + 0] - scoord[3 * i + 0];
        float b1y = scoord[3 * j + 1] - scoord[3 * i + 1];
        float b1z = scoord[3 * j + 2] - scoord[3 * i + 2];
        float b2x = scoord[3 * k + 0] - scoord[3 * j + 0];
        float b2y = scoord[3 * k + 1] - scoord[3 * j + 1];
        float b2z = scoord[3 * k + 2] - scoord[3 * j + 2];
        float b3x = scoord[3 * l + 0] - scoord[3 * k + 0];
        float b3y = scoord[3 * l + 1] - scoord[3 * k + 1];
        float b3z = scoord[3 * l + 2] - scoord[3 * k + 2];

        float n1x = b1y * b2z - b1z * b2y;
        float n1y = b1z * b2x - b1x * b2z;
        float n1z = b1x * b2y - b1y * b2x;
        float n2x = b2y * b3z - b2z * b3y;
        float n2y = b2z * b3x - b2x * b3z;
        float n2z = b2x * b3y - b2y * b3x;

        float inv = rsqrtf(b2x * b2x + b2y * b2y + b2z * b2z + EPSF);
        float hx = b2x * inv, hy = b2y * inv, hz = b2z * inv;

        float m1x = n1y * hz - n1z * hy;
        float m1y = n1z * hx - n1x * hz;
        float m1z = n1x * hy - n1y * hx;

        float sy = m1x * n2x + m1y * n2y + m1z * n2z;
        float sx = n1x * n2x + n1y * n2y + n1z * n2z;
        float phi = atan2f(sy, sx);

        int row = smap[NBT + NAT + ty];
        float kk = sopt[row * 3 + 0];
        float p0 = sopt[row * 3 + 1];
        float mu = sopt[row * 3 + 2];
        acc += kk * (1.0f + cosf(mu * phi - p0));
    }

    // ---- block reduction (512 threads = 16 warps) ----
    #pragma unroll
    for (int off = 16; off > 0; off >>= 1)
        acc += __shfl_down_sync(0xffffffffu, acc, off);
    if ((tid & 31) == 0) swarp[tid >> 5] = acc;
    __syncthreads();
    if (tid < 16) {
        float v = swarp[tid];
        #pragma unroll
        for (int off = 8; off > 0; off >>= 1)
            v += __shfl_down_sync(0xffffu, v, off);
        if (tid == 0) out[b] = v;
    }
}

extern "C" void kernel_launch(void* const* d_in, const int* in_sizes, int n_in,
                              void* d_out, int out_size)
{
    const float* feats   = (const float*)d_in[0];
    const int*   lengths = (const int*)  d_in[1];
    const float* opt     = (const float*)d_in[2];
    const float* btype   = (const float*)d_in[3];
    const float* atype   = (const float*)d_in[4];
    const float* ttype   = (const float*)d_in[5];
    float* out = (float*)d_out;

    cudaFuncSetAttribute(energy_kernel,
                         cudaFuncAttributeMaxDynamicSharedMemorySize, SMEM_BYTES);
    energy_kernel<<<BB, NTHR, SMEM_BYTES>>>(feats, lengths, opt, btype, atype,
                                            ttype, out);
}

// round 4
// speedup vs baseline: 6.4840x; 6.4840x over previous
#include <cuda_runtime.h>

#define BB      256
#define MAXLEN  10000
#define NWORDS  (MAXLEN * 9)        // 90000
#define NV4     (NWORDS / 4)        // 22500
#define NATOMS  2000
#define NBONDS  1999
#define NANG    1998
#define NTOR    1997
#define NBT     50
#define NAT     100
#define NTT     200
#define PTOT    (NBT + NAT + NTT)   // 350
#define EPSF    1e-8f
#define NTHR    512

#define N_COORD (3 * NATOMS)        // 6000 floats
#define N_BOND  (3 * NBONDS)        // 5997 shorts
#define N_ANGW  (4 * NANG)          // 7992 shorts
#define N_TORW  (5 * NTOR)          // 9985 shorts

// dynamic smem byte offsets
#define OFF_COORD 0
#define OFF_OPT   (OFF_COORD + N_COORD * 4)          // 24000
#define OFF_WARP  (OFF_OPT + PTOT * 3 * 4)           // 28200
#define OFF_MAP   (OFF_WARP + 16 * 4)                // 28264
#define OFF_SBOND (OFF_MAP + PTOT * 4)               // 29664
#define OFF_SANG  (OFF_SBOND + N_BOND * 2)           // 41658
#define OFF_STOR  (OFF_SANG + N_ANGW * 2)            // 57642
#define SMEM_BYTES (OFF_STOR + N_TORW * 2 + 8)       // ~77620

__global__ __launch_bounds__(NTHR)
void energy_kernel(const float* __restrict__ feats,
                   const int*   __restrict__ lengths,
                   const float* __restrict__ opt,
                   const float* __restrict__ btype,
                   const float* __restrict__ atype,
                   const float* __restrict__ ttype,
                   float*       __restrict__ out)
{
    extern __shared__ char smraw[];
    float* scoord = (float*)(smraw + OFF_COORD);
    float* sopt   = (float*)(smraw + OFF_OPT);
    float* swarp  = (float*)(smraw + OFF_WARP);
    int*   smap   = (int*)  (smraw + OFF_MAP);
    short* sbond  = (short*)(smraw + OFF_SBOND);
    short* sang   = (short*)(smraw + OFF_SANG);
    short* stor   = (short*)(smraw + OFF_STOR);

    const int b   = blockIdx.x;
    const int tid = threadIdx.x;
    const float4* f4 = (const float4*)(feats + (size_t)b * NWORDS);

    // ---- record-centric extraction: cols 5..8 of record m are words 9m+5..9m+8 ----
    #pragma unroll 2
    for (int m = tid; m < MAXLEN; m += NTHR) {
        int w0 = 9 * m + 5;
        int ai = w0 >> 2;
        int bi = min(ai + 1, NV4 - 1);
        float4 A  = f4[ai];
        float4 Bv = f4[bi];
        int p = w0 & 3;                 // = (m+1) & 3
        float v5 = (p == 0) ? A.x : (p == 1) ? A.y : (p == 2) ? A.z : A.w;
        float v6 = (p == 0) ? A.y : (p == 1) ? A.z : (p == 2) ? A.w : Bv.x;
        float v7 = (p == 0) ? A.z : (p == 1) ? A.w : (p == 2) ? Bv.x : Bv.y;
        float v8 = (p == 0) ? A.w : (p == 1) ? Bv.x : (p == 2) ? Bv.y : Bv.z;
        if (m < N_COORD) scoord[m] = v5;
        if (m < N_BOND)  sbond[m]  = (short)v6;
        if (m < N_ANGW)  sang[m]   = (short)v7;
        if (m < N_TORW)  stor[m]   = (short)v8;
    }
    // params + type maps
    for (int i = tid; i < PTOT * 3; i += NTHR)
        sopt[i] = opt[i];
    for (int i = tid; i < PTOT; i += NTHR) {
        float v;
        if      (i < NBT)       v = btype[i];
        else if (i < NBT + NAT) v = atype[i - NBT];
        else                    v = ttype[i - NBT - NAT];
        smap[i] = (int)v;
    }
    __syncthreads();

    const int nb = lengths[b * 9 + 6] / 3;
    const int na = lengths[b * 9 + 7] / 4;
    const int nt = lengths[b * 9 + 8] / 5;

    float acc = 0.0f;

    // ---- bonds: E = k * (r - r0)^2 ----
    for (int t = tid; t < NBONDS; t += NTHR) {
        if (t >= nb) continue;
        int i  = sbond[3 * t + 0];
        int j  = sbond[3 * t + 1];
        int ty = sbond[3 * t + 2];
        float dx = scoord[3 * i + 0] - scoord[3 * j + 0];
        float dy = scoord[3 * i + 1] - scoord[3 * j + 1];
        float dz = scoord[3 * i + 2] - scoord[3 * j + 2];
        float r  = sqrtf(dx * dx + dy * dy + dz * dz + EPSF);
        int row  = smap[ty];
        float d  = r - sopt[row * 3 + 1];
        acc += sopt[row * 3 + 0] * d * d;
    }

    // ---- angles: E = k * (theta - theta0)^2 ----
    for (int t = tid; t < NANG; t += NTHR) {
        if (t >= na) continue;
        int i  = sang[4 * t + 0];
        int j  = sang[4 * t + 1];
        int k  = sang[4 * t + 2];
        int ty = sang[4 * t + 3];
        float ux = scoord[3 * i + 0] - scoord[3 * j + 0];
        float uy = scoord[3 * i + 1] - scoord[3 * j + 1];
        float uz = scoord[3 * i + 2] - scoord[3 * j + 2];
        float vx = scoord[3 * k + 0] - scoord[3 * j + 0];
        float vy = scoord[3 * k + 1] - scoord[3 * j + 1];
        float vz = scoord[3 * k + 2] - scoord[3 * j + 2];
        float duv = ux * vx + uy * vy + uz * vz;
        float duu = ux * ux + uy * uy + uz * uz;
        float dvv = vx * vx + vy * vy + vz * vz;
        float c   = duv * rsqrtf((duu + EPSF) * (dvv + EPSF));
        c = fminf(fmaxf(c, -1.0f + 1e-6f), 1.0f - 1e-6f);
        float theta = acosf(c);
        int row = smap[NBT + ty];
        float d = theta - sopt[row * 3 + 1];
        acc += sopt[row * 3 + 0] * d * d;
    }

    // ---- torsions: E = k * (1 + cos(n*phi - phi0)) ----
    for (int t = tid; t < NTOR; t += NTHR) {
        if (t >= nt) continue;
        int i  = stor[5 * t + 0];
        int j  = stor[5 * t + 1];
        int k  = stor[5 * t + 2];
        int l  = stor[5 * t + 3];
        int ty = stor[5 * t + 4];

        float b1x = scoord[3 * j + 0] - scoord[3 * i + 0];
        float b1y = scoord[3 * j + 1] - scoord[3 * i + 1];
        float b1z = scoord[3 * j + 2] - scoord[3 * i + 2];
        float b2x = scoord[3 * k + 0] - scoord[3 * j + 0];
        float b2y = scoord[3 * k + 1] - scoord[3 * j + 1];
        float b2z = scoord[3 * k + 2] - scoord[3 * j + 2];
        float b3x = scoord[3 * l + 0] - scoord[3 * k + 0];
        float b3y = scoord[3 * l + 1] - scoord[3 * k + 1];
        float b3z = scoord[3 * l + 2] - scoord[3 * k + 2];

        float n1x = b1y * b2z - b1z * b2y;
        float n1y = b1z * b2x - b1x * b2z;
        float n1z = b1x * b2y - b1y * b2x;
        float n2x = b2y * b3z - b2z * b3y;
        float n2y = b2z * b3x - b2x * b3z;
        float n2z = b2x * b3y - b2y * b3x;

        float inv = rsqrtf(b2x * b2x + b2y * b2y + b2z * b2z + EPSF);
        float hx = b2x * inv, hy = b2y * inv, hz = b2z * inv;

        float m1x = n1y * hz - n1z * hy;
        float m1y = n1z * hx - n1x * hz;
        float m1z = n1x * hy - n1y * hx;

        float sy = m1x * n2x + m1y * n2y + m1z * n2z;
        float sx = n1x * n2x + n1y * n2y + n1z * n2z;
        float phi = atan2f(sy, sx);

        int row = smap[NBT + NAT + ty];
        float kk = sopt[row * 3 + 0];
        float p0 = sopt[row * 3 + 1];
        float mu = sopt[row * 3 + 2];
        acc += kk * (1.0f + cosf(mu * phi - p0));
    }

    // ---- block reduction (16 warps) ----
    #pragma unroll
    for (int off = 16; off > 0; off >>= 1)
        acc += __shfl_down_sync(0xffffffffu, acc, off);
    if ((tid & 31) == 0) swarp[tid >> 5] = acc;
    __syncthreads();
    if (tid < 16) {
        float v = swarp[tid];
        #pragma unroll
        for (int off = 8; off > 0; off >>= 1)
            v += __shfl_down_sync(0xffffu, v, off);
        if (tid == 0) out[b] = v;
    }
}

extern "C" void kernel_launch(void* const* d_in, const int* in_sizes, int n_in,
                              void* d_out, int out_size)
{
    const float* feats   = (const float*)d_in[0];
    const int*   lengths = (const int*)  d_in[1];
    const float* opt     = (const float*)d_in[2];
    const float* btype   = (const float*)d_in[3];
    const float* atype   = (const float*)d_in[4];
    const float* ttype   = (const float*)d_in[5];
    float* out = (float*)d_out;

    cudaFuncSetAttribute(energy_kernel,
                         cudaFuncAttributeMaxDynamicSharedMemorySize, SMEM_BYTES);
    energy_kernel<<<BB, NTHR, SMEM_BYTES>>>(feats, lengths, opt, btype, atype,
                                            ttype, out);
}

// round 6
// speedup vs baseline: 7.0902x; 1.0935x over previous
#include <cuda_runtime.h>

#define BB      256
#define MAXLEN  10000
#define NWORDS  (MAXLEN * 9)        // 90000
#define NV4     (NWORDS / 4)        // 22500
#define NATOMS  2000
#define NBONDS  1999
#define NANG    1998
#define NTOR    1997
#define NBT     50
#define NAT     100
#define NTT     200
#define PTOT    (NBT + NAT + NTT)   // 350
#define EPSF    1e-8f
#define NTHR    1024

#define N_COORD (3 * NATOMS)        // 6000 floats
#define N_BOND  (3 * NBONDS)        // 5997 shorts
#define N_ANGW  (4 * NANG)          // 7992 shorts
#define N_TORW  (5 * NTOR)          // 9985 shorts

// dynamic smem byte offsets
#define OFF_COORD 0
#define OFF_OPT   (OFF_COORD + N_COORD * 4)          // 24000
#define OFF_WARP  (OFF_OPT + PTOT * 3 * 4)           // 28200
#define OFF_MAP   (OFF_WARP + 32 * 4)                // 28328
#define OFF_SBOND (OFF_MAP + PTOT * 4)               // 29728
#define OFF_SANG  (OFF_SBOND + N_BOND * 2)           // 41722
#define OFF_STOR  (OFF_SANG + N_ANGW * 2)            // 57706
#define SMEM_BYTES (OFF_STOR + N_TORW * 2 + 8)       // 77684

__device__ __forceinline__ void demux(const float4& A, const float4& Bv, int p,
                                      float& v5, float& v6, float& v7, float& v8)
{
    v5 = (p == 0) ? A.x : (p == 1) ? A.y : (p == 2) ? A.z : A.w;
    v6 = (p == 0) ? A.y : (p == 1) ? A.z : (p == 2) ? A.w : Bv.x;
    v7 = (p == 0) ? A.z : (p == 1) ? A.w : (p == 2) ? Bv.x : Bv.y;
    v8 = (p == 0) ? A.w : (p == 1) ? Bv.x : (p == 2) ? Bv.y : Bv.z;
}

__device__ __forceinline__ void scatter(char* smraw, int m,
                                        float v5, float v6, float v7, float v8)
{
    float* scoord = (float*)(smraw + OFF_COORD);
    short* sbond  = (short*)(smraw + OFF_SBOND);
    short* sang   = (short*)(smraw + OFF_SANG);
    short* stor   = (short*)(smraw + OFF_STOR);
    if (m < N_COORD) scoord[m] = v5;
    if (m < N_BOND)  sbond[m]  = (short)v6;
    if (m < N_ANGW)  sang[m]   = (short)v7;
    if (m < N_TORW)  stor[m]   = (short)v8;
}

__global__ __launch_bounds__(NTHR)
void energy_kernel(const float* __restrict__ feats,
                   const int*   __restrict__ lengths,
                   const float* __restrict__ opt,
                   const float* __restrict__ btype,
                   const float* __restrict__ atype,
                   const float* __restrict__ ttype,
                   float*       __restrict__ out)
{
    extern __shared__ char smraw[];
    float* scoord = (float*)(smraw + OFF_COORD);
    float* sopt   = (float*)(smraw + OFF_OPT);
    float* swarp  = (float*)(smraw + OFF_WARP);
    int*   smap   = (int*)  (smraw + OFF_MAP);
    short* sbond  = (short*)(smraw + OFF_SBOND);
    short* sang   = (short*)(smraw + OFF_SANG);
    short* stor   = (short*)(smraw + OFF_STOR);

    const int b   = blockIdx.x;
    const int tid = threadIdx.x;
    const float4* f4 = (const float4*)(feats + (size_t)b * NWORDS);

    // ---- record-centric extraction, 2 records in flight per thread ----
    for (int m = tid; m < MAXLEN; m += 2 * NTHR) {
        int m2 = m + NTHR;
        bool has2 = (m2 < MAXLEN);

        int w0 = 9 * m + 5;
        int ai = w0 >> 2;
        int bi = min(ai + 1, NV4 - 1);
        float4 A1 = f4[ai];
        float4 B1 = f4[bi];

        float4 A2, B2;
        int p2 = 0;
        if (has2) {
            int w2 = 9 * m2 + 5;
            int a2 = w2 >> 2;
            int b2i = min(a2 + 1, NV4 - 1);
            A2 = f4[a2];
            B2 = f4[b2i];
            p2 = w2 & 3;
        }

        float v5, v6, v7, v8;
        demux(A1, B1, w0 & 3, v5, v6, v7, v8);
        scatter(smraw, m, v5, v6, v7, v8);

        if (has2) {
            demux(A2, B2, p2, v5, v6, v7, v8);
            scatter(smraw, m2, v5, v6, v7, v8);
        }
    }
    // params + type maps (PTOT*3 = 1050 > NTHR: must loop!)
    for (int i = tid; i < PTOT * 3; i += NTHR)
        sopt[i] = opt[i];
    for (int i = tid; i < PTOT; i += NTHR) {
        float v;
        if      (i < NBT)       v = btype[i];
        else if (i < NBT + NAT) v = atype[i - NBT];
        else                    v = ttype[i - NBT - NAT];
        smap[i] = (int)v;
    }
    __syncthreads();

    const int nb = lengths[b * 9 + 6] / 3;
    const int na = lengths[b * 9 + 7] / 4;
    const int nt = lengths[b * 9 + 8] / 5;

    float acc = 0.0f;

    // ---- bonds: E = k * (r - r0)^2 ----
    for (int t = tid; t < NBONDS; t += NTHR) {
        if (t >= nb) continue;
        int i  = sbond[3 * t + 0];
        int j  = sbond[3 * t + 1];
        int ty = sbond[3 * t + 2];
        float dx = scoord[3 * i + 0] - scoord[3 * j + 0];
        float dy = scoord[3 * i + 1] - scoord[3 * j + 1];
        float dz = scoord[3 * i + 2] - scoord[3 * j + 2];
        float r  = sqrtf(dx * dx + dy * dy + dz * dz + EPSF);
        int row  = smap[ty];
        float d  = r - sopt[row * 3 + 1];
        acc += sopt[row * 3 + 0] * d * d;
    }

    // ---- angles: E = k * (theta - theta0)^2 ----
    for (int t = tid; t < NANG; t += NTHR) {
        if (t >= na) continue;
        int i  = sang[4 * t + 0];
        int j  = sang[4 * t + 1];
        int k  = sang[4 * t + 2];
        int ty = sang[4 * t + 3];
        float ux = scoord[3 * i + 0] - scoord[3 * j + 0];
        float uy = scoord[3 * i + 1] - scoord[3 * j + 1];
        float uz = scoord[3 * i + 2] - scoord[3 * j + 2];
        float vx = scoord[3 * k + 0] - scoord[3 * j + 0];
        float vy = scoord[3 * k + 1] - scoord[3 * j + 1];
        float vz = scoord[3 * k + 2] - scoord[3 * j + 2];
        float duv = ux * vx + uy * vy + uz * vz;
        float duu = ux * ux + uy * uy + uz * uz;
        float dvv = vx * vx + vy * vy + vz * vz;
        float c   = duv * rsqrtf((duu + EPSF) * (dvv + EPSF));
        c = fminf(fmaxf(c, -1.0f + 1e-6f), 1.0f - 1e-6f);
        float theta = acosf(c);
        int row = smap[NBT + ty];
        float d = theta - sopt[row * 3 + 1];
        acc += sopt[row * 3 + 0] * d * d;
    }

    // ---- torsions: E = k * (1 + cos(n*phi - phi0)) ----
    for (int t = tid; t < NTOR; t += NTHR) {
        if (t >= nt) continue;
        int i  = stor[5 * t + 0];
        int j  = stor[5 * t + 1];
        int k  = stor[5 * t + 2];
        int l  = stor[5 * t + 3];
        int ty = stor[5 * t + 4];

        float b1x = scoord[3 * j + 0] - scoord[3 * i + 0];
        float b1y = scoord[3 * j + 1] - scoord[3 * i + 1];
        float b1z = scoord[3 * j + 2] - scoord[3 * i + 2];
        float b2x = scoord[3 * k + 0] - scoord[3 * j + 0];
        float b2y = scoord[3 * k + 1] - scoord[3 * j + 1];
        float b2z = scoord[3 * k + 2] - scoord[3 * j + 2];
        float b3x = scoord[3 * l + 0] - scoord[3 * k + 0];
        float b3y = scoord[3 * l + 1] - scoord[3 * k + 1];
        float b3z = scoord[3 * l + 2] - scoord[3 * k + 2];

        float n1x = b1y * b2z - b1z * b2y;
        float n1y = b1z * b2x - b1x * b2z;
        float n1z = b1x * b2y - b1y * b2x;
        float n2x = b2y * b3z - b2z * b3y;
        float n2y = b2z * b3x - b2x * b3z;
        float n2z = b2x * b3y - b2y * b3x;

        float inv = rsqrtf(b2x * b2x + b2y * b2y + b2z * b2z + EPSF);
        float hx = b2x * inv, hy = b2y * inv, hz = b2z * inv;

        float m1x = n1y * hz - n1z * hy;
        float m1y = n1z * hx - n1x * hz;
        float m1z = n1x * hy - n1y * hx;

        float sy = m1x * n2x + m1y * n2y + m1z * n2z;
        float sx = n1x * n2x + n1y * n2y + n1z * n2z;
        float phi = atan2f(sy, sx);

        int row = smap[NBT + NAT + ty];
        float kk = sopt[row * 3 + 0];
        float p0 = sopt[row * 3 + 1];
        float mu = sopt[row * 3 + 2];
        acc += kk * (1.0f + cosf(mu * phi - p0));
    }

    // ---- block reduction (32 warps) ----
    #pragma unroll
    for (int off = 16; off > 0; off >>= 1)
        acc += __shfl_down_sync(0xffffffffu, acc, off);
    if ((tid & 31) == 0) swarp[tid >> 5] = acc;
    __syncthreads();
    if (tid < 32) {
        float v = swarp[tid];
        #pragma unroll
        for (int off = 16; off > 0; off >>= 1)
            v += __shfl_down_sync(0xffffffffu, v, off);
        if (tid == 0) out[b] = v;
    }
}

extern "C" void kernel_launch(void* const* d_in, const int* in_sizes, int n_in,
                              void* d_out, int out_size)
{
    const float* feats   = (const float*)d_in[0];
    const int*   lengths = (const int*)  d_in[1];
    const float* opt     = (const float*)d_in[2];
    const float* btype   = (const float*)d_in[3];
    const float* atype   = (const float*)d_in[4];
    const float* ttype   = (const float*)d_in[5];
    float* out = (float*)d_out;

    cudaFuncSetAttribute(energy_kernel,
                         cudaFuncAttributeMaxDynamicSharedMemorySize, SMEM_BYTES);
    energy_kernel<<<BB, NTHR, SMEM_BYTES>>>(feats, lengths, opt, btype, atype,
                                            ttype, out);
}